// round 13
// baseline (speedup 1.0000x reference)
#include <cuda_runtime.h>
#include <cuda_bf16.h>
#include <cuda_fp16.h>
#include <math.h>

#define N_NODES 100000
#define N_EDGES 3200000
#define N_GRAPHS 64
#define F 16
#define NB ((N_NODES + 255) / 256)   // 391 blocks of 256

// ---------------- scratch (static device memory; no allocation) ----------------
// Invariant: d_deg, d_cnt, d_gsum, d_gcnt, d_total are ZERO before every launch
// (zero-initialized at load; each launch re-zeroes them after last use).
__device__ int    d_deg[N_NODES];        // out-degree over row (source)
__device__ int    d_cnt[N_NODES];        // in-count over col (target)
__device__ int    d_off[N_NODES];        // CSR offsets
__device__ int    d_cursor[N_NODES];     // scatter cursors
__device__ int    d_total;               // running base for block offsets
__device__ int2   d_csr[N_EDGES];        // {row, half2(ea.x, ea.y)}, grouped by col (8B)
__device__ int    d_row[N_EDGES];        // dense row copy (written by pull1, read by pull2)
__device__ float  d_dis[N_NODES];        // deg_inv_sqrt
__device__ uint2  d_xh[N_NODES];         // {half2(dis*x0, dis*x1), half2(dis*x2, dis)}
__device__ float2 d_zea[N_NODES];        // per-node Σ nr*ea (layer-independent)
__device__ float  d_h[N_NODES * F];      // layer-1 output (fp32, center path)
__device__ __half d_hh[N_NODES * F];     // dis[n]*h[n] fp16 shadow (gather path)
__device__ float  d_gsum[N_GRAPHS * F];  // pooled sums
__device__ int    d_gcnt[N_GRAPHS];      // nodes per graph

// ---------------- kernels ----------------

// histograms, 8 edges per thread (batched loads, 16 independent atomics in flight)
__global__ void k_hist(const int* __restrict__ ei) {
    int t = blockIdx.x * blockDim.x + threadIdx.x;
    int e = t * 8;
    if (e >= N_EDGES) return;            // N_EDGES % 8 == 0, no tail
    int4 ra = *(const int4*)&ei[e];
    int4 rb = *(const int4*)&ei[e + 4];
    int4 ca = *(const int4*)&ei[N_EDGES + e];
    int4 cb = *(const int4*)&ei[N_EDGES + e + 4];
    atomicAdd(&d_deg[ra.x], 1);
    atomicAdd(&d_deg[ra.y], 1);
    atomicAdd(&d_deg[ra.z], 1);
    atomicAdd(&d_deg[ra.w], 1);
    atomicAdd(&d_deg[rb.x], 1);
    atomicAdd(&d_deg[rb.y], 1);
    atomicAdd(&d_deg[rb.z], 1);
    atomicAdd(&d_deg[rb.w], 1);
    atomicAdd(&d_cnt[ca.x], 1);
    atomicAdd(&d_cnt[ca.y], 1);
    atomicAdd(&d_cnt[ca.z], 1);
    atomicAdd(&d_cnt[ca.w], 1);
    atomicAdd(&d_cnt[cb.x], 1);
    atomicAdd(&d_cnt[cb.y], 1);
    atomicAdd(&d_cnt[cb.z], 1);
    atomicAdd(&d_cnt[cb.w], 1);
}

// offsets via local scan + atomic block base (order-free), fused finalize.
// Stores premultiplied fp16-packed x features. Re-zeroes d_deg (last consumer).
__global__ void k_off(const float* __restrict__ x) {
    __shared__ int sm[256];
    __shared__ int base_sh;
    int t = threadIdx.x;
    int n = blockIdx.x * 256 + t;
    int c = (n < N_NODES) ? d_cnt[n] : 0;
    sm[t] = c;
    __syncthreads();
    for (int off = 1; off < 256; off <<= 1) {
        int v = (t >= off) ? sm[t - off] : 0;
        __syncthreads();
        sm[t] += v;
        __syncthreads();
    }
    if (t == 255) base_sh = atomicAdd(&d_total, sm[255]);
    __syncthreads();
    if (n < N_NODES) {
        int o = base_sh + sm[t] - c;   // exclusive within block + block base
        d_off[n] = o;
        d_cursor[n] = o;
        int dg = d_deg[n];
        d_deg[n] = 0;                  // restore invariant for next launch
        float dis = (dg > 0) ? rsqrtf((float)dg) : 0.0f;
        d_dis[n] = dis;
        __half2 p01 = __floats2half2_rn(dis * x[n * 3 + 0], dis * x[n * 3 + 1]);
        __half2 p23 = __floats2half2_rn(dis * x[n * 3 + 2], dis);
        uint2 pk;
        pk.x = *(unsigned int*)&p01;
        pk.y = *(unsigned int*)&p23;
        d_xh[n] = pk;
    }
}

// scatter edges grouped by target, 8 edges per thread; ONE STG.64 per edge
__global__ void k_scatter(const int* __restrict__ ei, const float* __restrict__ ea) {
    int t = blockIdx.x * blockDim.x + threadIdx.x;
    int e = t * 8;
    if (e >= N_EDGES) return;
    int4 ra = *(const int4*)&ei[e];
    int4 rb = *(const int4*)&ei[e + 4];
    int4 ca = *(const int4*)&ei[N_EDGES + e];
    int4 cb = *(const int4*)&ei[N_EDGES + e + 4];
    float4 ea0 = __ldg(&((const float4*)ea)[t * 4 + 0]);
    float4 ea1 = __ldg(&((const float4*)ea)[t * 4 + 1]);
    float4 ea2 = __ldg(&((const float4*)ea)[t * 4 + 2]);
    float4 ea3 = __ldg(&((const float4*)ea)[t * 4 + 3]);
    __half2 h0 = __floats2half2_rn(ea0.x, ea0.y);
    __half2 h1 = __floats2half2_rn(ea0.z, ea0.w);
    __half2 h2 = __floats2half2_rn(ea1.x, ea1.y);
    __half2 h3 = __floats2half2_rn(ea1.z, ea1.w);
    __half2 h4 = __floats2half2_rn(ea2.x, ea2.y);
    __half2 h5 = __floats2half2_rn(ea2.z, ea2.w);
    __half2 h6 = __floats2half2_rn(ea3.x, ea3.y);
    __half2 h7 = __floats2half2_rn(ea3.z, ea3.w);
    int p0 = atomicAdd(&d_cursor[ca.x], 1);
    int p1 = atomicAdd(&d_cursor[ca.y], 1);
    int p2 = atomicAdd(&d_cursor[ca.z], 1);
    int p3 = atomicAdd(&d_cursor[ca.w], 1);
    int p4 = atomicAdd(&d_cursor[cb.x], 1);
    int p5 = atomicAdd(&d_cursor[cb.y], 1);
    int p6 = atomicAdd(&d_cursor[cb.z], 1);
    int p7 = atomicAdd(&d_cursor[cb.w], 1);
    d_csr[p0] = make_int2(ra.x, *(int*)&h0);
    d_csr[p1] = make_int2(ra.y, *(int*)&h1);
    d_csr[p2] = make_int2(ra.z, *(int*)&h2);
    d_csr[p3] = make_int2(ra.w, *(int*)&h3);
    d_csr[p4] = make_int2(rb.x, *(int*)&h4);
    d_csr[p5] = make_int2(rb.y, *(int*)&h5);
    d_csr[p6] = make_int2(rb.z, *(int*)&h6);
    d_csr[p7] = make_int2(rb.w, *(int*)&h7);
}

// layer-1 pull: 8 lanes per node (4 nodes per warp), fp16 premultiplied gathers.
// Also writes dense d_row for pull2's sector-efficient read.
__global__ void k_pull1(const float* __restrict__ x,
                        const float* __restrict__ Wn1,
                        const float* __restrict__ Wc1,
                        const float* __restrict__ bc1) {
    int idx = blockIdx.x * blockDim.x + threadIdx.x;
    int n = idx >> 3;                   // 8 lanes per node
    if (n >= N_NODES) return;
    int sub = threadIdx.x & 7;
    int start = d_off[n];
    int cnt = d_cnt[n];
    int end = start + cnt;
    float a0 = 0.f, a1 = 0.f, a2 = 0.f, a3 = 0.f, a4 = 0.f;
    for (int i = start + sub; i < end; i += 8) {
        int2 en = d_csr[i];
        d_row[i] = en.x;                // dense row copy (coalesced within segment)
        uint2 xv = __ldg(&d_xh[en.x]);  // {dis*x0, dis*x1 | dis*x2, dis}
        float2 f01 = __half22float2(*(__half2*)&xv.x);
        float2 f23 = __half22float2(*(__half2*)&xv.y);
        float2 eav = __half22float2(*(__half2*)&en.y);
        a0 += f01.x;
        a1 += f01.y;
        a2 += f23.x;
        a3 += f23.y * eav.x;
        a4 += f23.y * eav.y;
    }
#pragma unroll
    for (int o = 4; o; o >>= 1) {       // stays within the 8-lane group
        a0 += __shfl_xor_sync(0xffffffffu, a0, o);
        a1 += __shfl_xor_sync(0xffffffffu, a1, o);
        a2 += __shfl_xor_sync(0xffffffffu, a2, o);
        a3 += __shfl_xor_sync(0xffffffffu, a3, o);
        a4 += __shfl_xor_sync(0xffffffffu, a4, o);
    }
    float disc = d_dis[n];
    float ci = 1.0f / (float)(cnt > 0 ? cnt : 1);
    float dc = disc * ci;
    if (sub == 0) d_zea[n] = make_float2(disc * a3, disc * a4);
    float x0 = __ldg(&x[n * 3 + 0]), x1 = __ldg(&x[n * 3 + 1]), x2 = __ldg(&x[n * 3 + 2]);
#pragma unroll
    for (int q = 0; q < 2; q++) {       // each lane covers columns sub and sub+8
        int j = sub + q * 8;
        float aggr = dc * (a0 * __ldg(&Wn1[0 * F + j]) + a1 * __ldg(&Wn1[1 * F + j]) +
                           a2 * __ldg(&Wn1[2 * F + j]) + a3 * __ldg(&Wn1[3 * F + j]) +
                           a4 * __ldg(&Wn1[4 * F + j]));
        float cent = __ldg(&bc1[j]) + x0 * __ldg(&Wc1[0 * F + j]) +
                     x1 * __ldg(&Wc1[1 * F + j]) + x2 * __ldg(&Wc1[2 * F + j]);
        float v = fmaxf(cent + aggr, 0.0f);
        d_h[n * F + j] = v;
        d_hh[n * F + j] = __float2half(disc * v);   // premultiplied shadow
    }
}

// layer-2 pull: 16 lanes per node (2 nodes per warp), pure fp16 gather-accumulate
__global__ void k_pull2(const float* __restrict__ Wn2,
                        const float* __restrict__ Wc2,
                        const float* __restrict__ bc2,
                        const int* __restrict__ batch) {
    int idx = blockIdx.x * blockDim.x + threadIdx.x;
    int n = idx >> 4;                   // 16 lanes per node
    if (n >= N_NODES) return;
    int sub = threadIdx.x & 15;
    int start = d_off[n];
    int cnt = d_cnt[n];
    int end = start + cnt;
    float acc[F];
#pragma unroll
    for (int k = 0; k < F; k++) acc[k] = 0.0f;
    for (int i = start + sub; i < end; i += 16) {
        int r = __ldg(&d_row[i]);       // dense, 100% sector efficiency
        const uint4* hp = (const uint4*)&d_hh[r * F];
        uint4 u0 = __ldg(&hp[0]);       // halves 0..7  (already dis_r-scaled)
        uint4 u1 = __ldg(&hp[1]);       // halves 8..15
        const __half2* p0 = (const __half2*)&u0;
        const __half2* p1 = (const __half2*)&u1;
#pragma unroll
        for (int w = 0; w < 4; w++) {
            float2 f = __half22float2(p0[w]);
            acc[2 * w + 0] += f.x;
            acc[2 * w + 1] += f.y;
        }
#pragma unroll
        for (int w = 0; w < 4; w++) {
            float2 f = __half22float2(p1[w]);
            acc[8 + 2 * w + 0] += f.x;
            acc[8 + 2 * w + 1] += f.y;
        }
    }
#pragma unroll
    for (int o = 8; o; o >>= 1) {       // stays within the 16-lane group
#pragma unroll
        for (int k = 0; k < F; k++) acc[k] += __shfl_xor_sync(0xffffffffu, acc[k], o);
    }
    int g = __ldg(&batch[n]);
    if (sub == 1) d_cnt[n] = 0;         // restore invariant for next launch
    if (sub == 2) atomicAdd(&d_gcnt[g], 1);
    {
        int j = sub;
        float disc = d_dis[n];
        float ci = 1.0f / (float)(cnt > 0 ? cnt : 1);
        float2 zea = d_zea[n];
        float s = 0.0f;
#pragma unroll
        for (int k = 0; k < F; k++) s += acc[k] * __ldg(&Wn2[k * F + j]);
        float aggr = (zea.x * __ldg(&Wn2[16 * F + j]) +
                      zea.y * __ldg(&Wn2[17 * F + j]) + disc * s) * ci;
        float cent = __ldg(&bc2[j]);
        const float* hn = &d_h[n * F];
#pragma unroll
        for (int k = 0; k < F; k++) cent += hn[k] * __ldg(&Wc2[k * F + j]);
        float v = fmaxf(cent + aggr, 0.0f);
        atomicAdd(&d_gsum[g * F + j], v);
    }
}

// head MLP (mean + 2-layer MLP); re-zeroes d_gsum/d_gcnt/d_total
__global__ void k_head(const float* __restrict__ Wl1, const float* __restrict__ bl1,
                       const float* __restrict__ Wl2, const float* __restrict__ bl2,
                       float* __restrict__ out) {
    int g = threadIdx.x;
    if (g >= N_GRAPHS) return;
    if (g == 0) d_total = 0;           // restore invariant for next launch
    int c = d_gcnt[g];
    d_gcnt[g] = 0;
    float inv = 1.0f / (float)(c > 0 ? c : 1);
    float gm[F];
#pragma unroll
    for (int k = 0; k < F; k++) {
        gm[k] = d_gsum[g * F + k] * inv;
        d_gsum[g * F + k] = 0.0f;
    }
    float t[F];
#pragma unroll
    for (int j = 0; j < F; j++) {
        float a = bl1[j];
#pragma unroll
        for (int k = 0; k < F; k++) a += gm[k] * Wl1[k * F + j];
        t[j] = fmaxf(a, 0.0f);
    }
#pragma unroll
    for (int o = 0; o < 2; o++) {
        float a = bl2[o];
#pragma unroll
        for (int j = 0; j < F; j++) a += t[j] * Wl2[j * 2 + o];
        out[g * 2 + o] = a;
    }
}

// ---------------- launch ----------------
extern "C" void kernel_launch(void* const* d_in, const int* in_sizes, int n_in,
                              void* d_out, int out_size) {
    const float* x     = (const float*)d_in[0];
    const int*   ei    = (const int*)d_in[1];
    const float* ea    = (const float*)d_in[2];
    const int*   batch = (const int*)d_in[3];
    const float* Wc1 = (const float*)d_in[4];
    const float* bc1 = (const float*)d_in[5];
    const float* Wn1 = (const float*)d_in[6];
    const float* Wc2 = (const float*)d_in[7];
    const float* bc2 = (const float*)d_in[8];
    const float* Wn2 = (const float*)d_in[9];
    const float* Wl1 = (const float*)d_in[10];
    const float* bl1 = (const float*)d_in[11];
    const float* Wl2 = (const float*)d_in[12];
    const float* bl2 = (const float*)d_in[13];
    float* out = (float*)d_out;

    const int T = 256;
    int eb8 = (N_EDGES / 8 + T - 1) / T;     // 8 edges per thread
    int p1b = (N_NODES * 8 + T - 1) / T;     // 8 lanes per node  (=3125)
    int p2b = (N_NODES * 16 + T - 1) / T;    // 16 lanes per node (=6250)

    k_hist<<<eb8, T>>>(ei);
    k_off<<<NB, T>>>(x);
    k_scatter<<<eb8, T>>>(ei, ea);
    k_pull1<<<p1b, T>>>(x, Wn1, Wc1, bc1);
    k_pull2<<<p2b, T>>>(Wn2, Wc2, bc2, batch);
    k_head<<<1, 64>>>(Wl1, bl1, Wl2, bl2, out);
}

// round 14
// speedup vs baseline: 1.0487x; 1.0487x over previous
#include <cuda_runtime.h>
#include <cuda_bf16.h>
#include <cuda_fp16.h>
#include <math.h>

#define N_NODES 100000
#define N_EDGES 3200000
#define N_GRAPHS 64
#define F 16
#define NB ((N_NODES + 255) / 256)   // 391 blocks of 256

// ---------------- scratch (static device memory; no allocation) ----------------
// Invariant: d_deg, d_cnt, d_gsum, d_gcnt, d_total are ZERO before every launch
// (zero-initialized at load; each launch re-zeroes them after last use).
__device__ int    d_deg[N_NODES];        // out-degree over row (source)
__device__ int    d_cnt[N_NODES];        // in-count over col (target)
__device__ int    d_off[N_NODES];        // CSR offsets
__device__ int    d_rank[N_EDGES];       // edge rank within its target segment (from hist)
__device__ int    d_total;               // running base for block offsets
__device__ int2   d_csr[N_EDGES];        // {row, half2(ea.x, ea.y)}, grouped by col (8B)
__device__ float  d_dis[N_NODES];        // deg_inv_sqrt
__device__ uint2  d_xh[N_NODES];         // {half2(dis*x0, dis*x1), half2(dis*x2, dis)}
__device__ float2 d_zea[N_NODES];        // per-node Σ nr*ea (layer-independent)
__device__ float  d_h[N_NODES * F];      // layer-1 output (fp32, center path)
__device__ __half d_hh[N_NODES * F];     // dis[n]*h[n] fp16 shadow (gather path)
__device__ float  d_gsum[N_GRAPHS * F];  // pooled sums
__device__ int    d_gcnt[N_GRAPHS];      // nodes per graph

// ---------------- kernels ----------------

// histograms, 4 edges per thread; keeps the cnt-atomic return as the edge's rank
__global__ void k_hist(const int* __restrict__ ei) {
    int t = blockIdx.x * blockDim.x + threadIdx.x;
    int e = t * 4;
    if (e >= N_EDGES) return;            // N_EDGES % 4 == 0, no tail
    int4 r4 = *(const int4*)&ei[e];
    int4 c4 = *(const int4*)&ei[N_EDGES + e];
    atomicAdd(&d_deg[r4.x], 1);
    atomicAdd(&d_deg[r4.y], 1);
    atomicAdd(&d_deg[r4.z], 1);
    atomicAdd(&d_deg[r4.w], 1);
    int4 rk;
    rk.x = atomicAdd(&d_cnt[c4.x], 1);
    rk.y = atomicAdd(&d_cnt[c4.y], 1);
    rk.z = atomicAdd(&d_cnt[c4.z], 1);
    rk.w = atomicAdd(&d_cnt[c4.w], 1);
    *(int4*)&d_rank[e] = rk;             // coalesced
}

// offsets via local scan + atomic block base (order-free), fused finalize.
// Stores premultiplied fp16-packed x features. Re-zeroes d_deg (last consumer).
__global__ void k_off(const float* __restrict__ x) {
    __shared__ int sm[256];
    __shared__ int base_sh;
    int t = threadIdx.x;
    int n = blockIdx.x * 256 + t;
    int c = (n < N_NODES) ? d_cnt[n] : 0;
    sm[t] = c;
    __syncthreads();
    for (int off = 1; off < 256; off <<= 1) {
        int v = (t >= off) ? sm[t - off] : 0;
        __syncthreads();
        sm[t] += v;
        __syncthreads();
    }
    if (t == 255) base_sh = atomicAdd(&d_total, sm[255]);
    __syncthreads();
    if (n < N_NODES) {
        int o = base_sh + sm[t] - c;   // exclusive within block + block base
        d_off[n] = o;
        int dg = d_deg[n];
        d_deg[n] = 0;                  // restore invariant for next launch
        float dis = (dg > 0) ? rsqrtf((float)dg) : 0.0f;
        d_dis[n] = dis;
        __half2 p01 = __floats2half2_rn(dis * x[n * 3 + 0], dis * x[n * 3 + 1]);
        __half2 p23 = __floats2half2_rn(dis * x[n * 3 + 2], dis);
        uint2 pk;
        pk.x = *(unsigned int*)&p01;
        pk.y = *(unsigned int*)&p23;
        d_xh[n] = pk;
    }
}

// scatter edges grouped by target, 4 edges per thread; ATOMIC-FREE:
// pos = off[col] + rank[e]; one STG.64 per edge.
__global__ void k_scatter(const int* __restrict__ ei, const float* __restrict__ ea) {
    int t = blockIdx.x * blockDim.x + threadIdx.x;
    int e = t * 4;
    if (e >= N_EDGES) return;
    int4 r4 = *(const int4*)&ei[e];
    int4 c4 = *(const int4*)&ei[N_EDGES + e];
    int4 rk = *(const int4*)&d_rank[e];
    float4 ea01 = __ldg(&((const float4*)ea)[t * 2 + 0]);   // ea[e], ea[e+1]
    float4 ea23 = __ldg(&((const float4*)ea)[t * 2 + 1]);   // ea[e+2], ea[e+3]
    __half2 h0 = __floats2half2_rn(ea01.x, ea01.y);
    __half2 h1 = __floats2half2_rn(ea01.z, ea01.w);
    __half2 h2 = __floats2half2_rn(ea23.x, ea23.y);
    __half2 h3 = __floats2half2_rn(ea23.z, ea23.w);
    int p0 = __ldg(&d_off[c4.x]) + rk.x;
    int p1 = __ldg(&d_off[c4.y]) + rk.y;
    int p2 = __ldg(&d_off[c4.z]) + rk.z;
    int p3 = __ldg(&d_off[c4.w]) + rk.w;
    d_csr[p0] = make_int2(r4.x, *(int*)&h0);
    d_csr[p1] = make_int2(r4.y, *(int*)&h1);
    d_csr[p2] = make_int2(r4.z, *(int*)&h2);
    d_csr[p3] = make_int2(r4.w, *(int*)&h3);
}

// layer-1 pull: 8 lanes per node (4 nodes per warp), fp16 premultiplied gathers
// h = relu(x@Wc1+bc1 + (disc*[Σ dis_r*x_r, Σ dis_r*ea]@Wn1)*cinv)
__global__ void k_pull1(const float* __restrict__ x,
                        const float* __restrict__ Wn1,
                        const float* __restrict__ Wc1,
                        const float* __restrict__ bc1) {
    int idx = blockIdx.x * blockDim.x + threadIdx.x;
    int n = idx >> 3;                   // 8 lanes per node
    if (n >= N_NODES) return;
    int sub = threadIdx.x & 7;
    int start = d_off[n];
    int cnt = d_cnt[n];
    int end = start + cnt;
    float a0 = 0.f, a1 = 0.f, a2 = 0.f, a3 = 0.f, a4 = 0.f;
    for (int i = start + sub; i < end; i += 8) {
        int2 en = d_csr[i];
        uint2 xv = __ldg(&d_xh[en.x]);  // {dis*x0, dis*x1 | dis*x2, dis}
        float2 f01 = __half22float2(*(__half2*)&xv.x);
        float2 f23 = __half22float2(*(__half2*)&xv.y);
        float2 eav = __half22float2(*(__half2*)&en.y);
        a0 += f01.x;
        a1 += f01.y;
        a2 += f23.x;
        a3 += f23.y * eav.x;
        a4 += f23.y * eav.y;
    }
#pragma unroll
    for (int o = 4; o; o >>= 1) {       // stays within the 8-lane group
        a0 += __shfl_xor_sync(0xffffffffu, a0, o);
        a1 += __shfl_xor_sync(0xffffffffu, a1, o);
        a2 += __shfl_xor_sync(0xffffffffu, a2, o);
        a3 += __shfl_xor_sync(0xffffffffu, a3, o);
        a4 += __shfl_xor_sync(0xffffffffu, a4, o);
    }
    float disc = d_dis[n];
    float ci = 1.0f / (float)(cnt > 0 ? cnt : 1);
    float dc = disc * ci;
    if (sub == 0) d_zea[n] = make_float2(disc * a3, disc * a4);
    float x0 = __ldg(&x[n * 3 + 0]), x1 = __ldg(&x[n * 3 + 1]), x2 = __ldg(&x[n * 3 + 2]);
#pragma unroll
    for (int q = 0; q < 2; q++) {       // each lane covers columns sub and sub+8
        int j = sub + q * 8;
        float aggr = dc * (a0 * __ldg(&Wn1[0 * F + j]) + a1 * __ldg(&Wn1[1 * F + j]) +
                           a2 * __ldg(&Wn1[2 * F + j]) + a3 * __ldg(&Wn1[3 * F + j]) +
                           a4 * __ldg(&Wn1[4 * F + j]));
        float cent = __ldg(&bc1[j]) + x0 * __ldg(&Wc1[0 * F + j]) +
                     x1 * __ldg(&Wc1[1 * F + j]) + x2 * __ldg(&Wc1[2 * F + j]);
        float v = fmaxf(cent + aggr, 0.0f);
        d_h[n * F + j] = v;
        d_hh[n * F + j] = __float2half(disc * v);   // premultiplied shadow
    }
}

// layer-2 pull: 16 lanes per node (2 nodes per warp), pure fp16 gather-accumulate
__global__ void k_pull2(const float* __restrict__ Wn2,
                        const float* __restrict__ Wc2,
                        const float* __restrict__ bc2,
                        const int* __restrict__ batch) {
    int idx = blockIdx.x * blockDim.x + threadIdx.x;
    int n = idx >> 4;                   // 16 lanes per node
    if (n >= N_NODES) return;
    int sub = threadIdx.x & 15;
    int start = d_off[n];
    int cnt = d_cnt[n];
    int end = start + cnt;
    float acc[F];
#pragma unroll
    for (int k = 0; k < F; k++) acc[k] = 0.0f;
    for (int i = start + sub; i < end; i += 16) {
        int r = d_csr[i].x;
        const uint4* hp = (const uint4*)&d_hh[r * F];
        uint4 u0 = __ldg(&hp[0]);       // halves 0..7  (already dis_r-scaled)
        uint4 u1 = __ldg(&hp[1]);       // halves 8..15
        const __half2* p0 = (const __half2*)&u0;
        const __half2* p1 = (const __half2*)&u1;
#pragma unroll
        for (int w = 0; w < 4; w++) {
            float2 f = __half22float2(p0[w]);
            acc[2 * w + 0] += f.x;
            acc[2 * w + 1] += f.y;
        }
#pragma unroll
        for (int w = 0; w < 4; w++) {
            float2 f = __half22float2(p1[w]);
            acc[8 + 2 * w + 0] += f.x;
            acc[8 + 2 * w + 1] += f.y;
        }
    }
#pragma unroll
    for (int o = 8; o; o >>= 1) {       // stays within the 16-lane group
#pragma unroll
        for (int k = 0; k < F; k++) acc[k] += __shfl_xor_sync(0xffffffffu, acc[k], o);
    }
    int g = __ldg(&batch[n]);
    if (sub == 1) d_cnt[n] = 0;         // restore invariant for next launch
    if (sub == 2) atomicAdd(&d_gcnt[g], 1);
    {
        int j = sub;
        float disc = d_dis[n];
        float ci = 1.0f / (float)(cnt > 0 ? cnt : 1);
        float2 zea = d_zea[n];
        float s = 0.0f;
#pragma unroll
        for (int k = 0; k < F; k++) s += acc[k] * __ldg(&Wn2[k * F + j]);
        float aggr = (zea.x * __ldg(&Wn2[16 * F + j]) +
                      zea.y * __ldg(&Wn2[17 * F + j]) + disc * s) * ci;
        float cent = __ldg(&bc2[j]);
        const float* hn = &d_h[n * F];
#pragma unroll
        for (int k = 0; k < F; k++) cent += hn[k] * __ldg(&Wc2[k * F + j]);
        float v = fmaxf(cent + aggr, 0.0f);
        atomicAdd(&d_gsum[g * F + j], v);
    }
}

// head MLP (mean + 2-layer MLP); re-zeroes d_gsum/d_gcnt/d_total
__global__ void k_head(const float* __restrict__ Wl1, const float* __restrict__ bl1,
                       const float* __restrict__ Wl2, const float* __restrict__ bl2,
                       float* __restrict__ out) {
    int g = threadIdx.x;
    if (g >= N_GRAPHS) return;
    if (g == 0) d_total = 0;           // restore invariant for next launch
    int c = d_gcnt[g];
    d_gcnt[g] = 0;
    float inv = 1.0f / (float)(c > 0 ? c : 1);
    float gm[F];
#pragma unroll
    for (int k = 0; k < F; k++) {
        gm[k] = d_gsum[g * F + k] * inv;
        d_gsum[g * F + k] = 0.0f;
    }
    float t[F];
#pragma unroll
    for (int j = 0; j < F; j++) {
        float a = bl1[j];
#pragma unroll
        for (int k = 0; k < F; k++) a += gm[k] * Wl1[k * F + j];
        t[j] = fmaxf(a, 0.0f);
    }
#pragma unroll
    for (int o = 0; o < 2; o++) {
        float a = bl2[o];
#pragma unroll
        for (int j = 0; j < F; j++) a += t[j] * Wl2[j * 2 + o];
        out[g * 2 + o] = a;
    }
}

// ---------------- launch ----------------
extern "C" void kernel_launch(void* const* d_in, const int* in_sizes, int n_in,
                              void* d_out, int out_size) {
    const float* x     = (const float*)d_in[0];
    const int*   ei    = (const int*)d_in[1];
    const float* ea    = (const float*)d_in[2];
    const int*   batch = (const int*)d_in[3];
    const float* Wc1 = (const float*)d_in[4];
    const float* bc1 = (const float*)d_in[5];
    const float* Wn1 = (const float*)d_in[6];
    const float* Wc2 = (const float*)d_in[7];
    const float* bc2 = (const float*)d_in[8];
    const float* Wn2 = (const float*)d_in[9];
    const float* Wl1 = (const float*)d_in[10];
    const float* bl1 = (const float*)d_in[11];
    const float* Wl2 = (const float*)d_in[12];
    const float* bl2 = (const float*)d_in[13];
    float* out = (float*)d_out;

    const int T = 256;
    int eb4 = (N_EDGES / 4 + T - 1) / T;     // 4 edges per thread
    int p1b = (N_NODES * 8 + T - 1) / T;     // 8 lanes per node  (=3125)
    int p2b = (N_NODES * 16 + T - 1) / T;    // 16 lanes per node (=6250)

    k_hist<<<eb4, T>>>(ei);
    k_off<<<NB, T>>>(x);
    k_scatter<<<eb4, T>>>(ei, ea);
    k_pull1<<<p1b, T>>>(x, Wn1, Wc1, bc1);
    k_pull2<<<p2b, T>>>(Wn2, Wc2, bc2, batch);
    k_head<<<1, 64>>>(Wl1, bl1, Wl2, bl2, out);
}